// round 9
// baseline (speedup 1.0000x reference)
#include <cuda_runtime.h>
#include <cuda_fp16.h>
#include <cstdint>
#include <cfloat>

#define W_TOTAL   262144
#define L_DIM     512
#define G_DIM     128
#define TILE_ROWS 128
#define NUM_TILES (W_TOTAL / TILE_ROWS)   // 2048
#define NK16      32                      // K=512 in 32 steps of 16
#define NTHREADS  512
#define ADEPTH    8                       // A register pipeline depth (k16 steps)

// ---- smem layout (bytes), dynamic smem only ----
#define OFF_B      0                  // B fp16, 8 slots x [128n][64k] = 128 KB (loaded once)
#define OFF_SSC    0                  // epilogue reuse: float[128][132] = 67584
#define SSC_PITCH  132
#define OFF_SB     131072             // bias 128 f32
#define OFF_SPRE   131584             // tile prefix 128 f32
#define OFF_STATE  132096             // lookback window state (int)
#define SMEM_TOTAL 132112

// device globals (no runtime allocation allowed)
__device__ __half g_Wh[G_DIM * L_DIM];          // W1^T as fp16, [n][k] k-major
__device__ float  g_aggregate[NUM_TILES * G_DIM];
__device__ float  g_inclusive[NUM_TILES * G_DIM];
__device__ int    g_flags[NUM_TILES];

#define SW128(o) ((o) ^ (((o) >> 3) & 0x70))

// ---- PTX helpers ----
__device__ __forceinline__ uint32_t smem_u32(const void* p) {
    uint32_t a;
    asm("{ .reg .u64 t; cvta.to.shared.u64 t, %1; cvt.u32.u64 %0, t; }" : "=r"(a) : "l"(p));
    return a;
}
__device__ __forceinline__ void ldsm_x4(uint32_t& r0, uint32_t& r1, uint32_t& r2,
                                        uint32_t& r3, uint32_t addr) {
    asm volatile("ldmatrix.sync.aligned.m8n8.x4.shared.b16 {%0,%1,%2,%3}, [%4];"
                 : "=r"(r0), "=r"(r1), "=r"(r2), "=r"(r3) : "r"(addr));
}
__device__ __forceinline__ void mma_f16(float* c, const uint32_t* a, uint32_t b0, uint32_t b1) {
    asm volatile(
        "mma.sync.aligned.m16n8k16.row.col.f32.f16.f16.f32 "
        "{%0,%1,%2,%3}, {%4,%5,%6,%7}, {%8,%9}, {%0,%1,%2,%3};"
        : "+f"(c[0]), "+f"(c[1]), "+f"(c[2]), "+f"(c[3])
        : "r"(a[0]), "r"(a[1]), "r"(a[2]), "r"(a[3]), "r"(b0), "r"(b1));
}
__device__ __forceinline__ void cp_async16(uint32_t dst, const void* src) {
    asm volatile("cp.async.cg.shared.global [%0], [%1], 16;" :: "r"(dst), "l"(src));
}
#define CP_COMMIT() asm volatile("cp.async.commit_group;" ::: "memory")
#define CP_WAIT0()  asm volatile("cp.async.wait_group 0;" ::: "memory")

__device__ __forceinline__ int ld_flag_cg(const int* p) {
    int f; asm volatile("ld.global.cg.b32 %0, [%1];" : "=r"(f) : "l"(p)); return f;
}
__device__ __forceinline__ float ld_f_cg(const float* p) {
    float f; asm volatile("ld.global.cg.f32 %0, [%1];" : "=f"(f) : "l"(p)); return f;
}
__device__ __forceinline__ void st_cs4(float* p, float4 v) {
    asm volatile("st.global.cs.v4.f32 [%0], {%1,%2,%3,%4};"
                 :: "l"(p), "f"(v.x), "f"(v.y), "f"(v.z), "f"(v.w) : "memory");
}
__device__ __forceinline__ float2 ldg2(const float* p) {
    float2 v;
    asm volatile("ld.global.nc.v2.f32 {%0,%1}, [%2];" : "=f"(v.x), "=f"(v.y) : "l"(p));
    return v;
}

// ---- merged prep kernel (1 launch): W1 -> fp16 transpose, zero flags ----
__global__ void prep_kernel(const float* __restrict__ W1) {   // W1: [512][128]
    int idx = blockIdx.x * 256 + threadIdx.x;                 // 65536
    int k = idx >> 7, n = idx & 127;
    g_Wh[n * L_DIM + k] = __float2half_rn(W1[idx]);
    if (idx < NUM_TILES) g_flags[idx] = 0;
}

// ---- main fused kernel: barrier-free fragment-direct GEMM + cummax lookback ----
__global__ void __launch_bounds__(NTHREADS, 1)
key_pool_mma(const float* __restrict__ A,      // [W, L]
             const float* __restrict__ gfeat,  // [G]
             const float* __restrict__ b1,     // [G]
             float* __restrict__ out, int write_tail) {
    extern __shared__ char sm[];
    const uint32_t smb = smem_u32(sm);
    float* Ssc   = (float*)(sm + OFF_SSC);
    float* Sb    = (float*)(sm + OFF_SB);
    float* Spre  = (float*)(sm + OFF_SPRE);
    int*   Sstat = (int*)(sm + OFF_STATE);

    const int tid  = threadIdx.x;
    const int wid  = tid >> 5;
    const int lane = tid & 31;
    const int tile = blockIdx.x;

    const int Rw = (wid & 7) * 16;   // warp row base (0..112)
    const int Cw = (wid >> 3) * 64;  // warp col base (0 or 64)

    const __half* Wh = g_Wh;

    // ---- prologue: cp.async ALL of B (128 KB), start A register pipeline ----
    #pragma unroll
    for (int i = 0; i < 16; ++i) {
        int e = tid + i * NTHREADS;              // 0..8191 uint4
        int slot = e >> 10, w = e & 1023;
        int n = w >> 3, u = w & 7;
        cp_async16(smb + OFF_B + slot * 16384 + SW128((uint32_t)(n * 128 + u * 16)),
                   Wh + n * L_DIM + slot * 64 + u * 8);
    }
    CP_COMMIT();

    // per-thread A fragment source pointer: row g = Rw + lane>>2, col base (lane&3)*2
    const float* pA = A + (size_t)tile * TILE_ROWS * L_DIM
                        + (size_t)(Rw + (lane >> 2)) * L_DIM + (lane & 3) * 2;

    float acc[8][4];
    #pragma unroll
    for (int n = 0; n < 8; ++n)
        #pragma unroll
        for (int j = 0; j < 4; ++j) acc[n][j] = 0.f;

    // A raw register pipeline: ADEPTH k16-steps, 4 float2 each
    float2 raw[ADEPTH][4];
    #pragma unroll
    for (int d = 0; d < ADEPTH; ++d) {
        const float* p = pA + d * 16;
        raw[d][0] = ldg2(p);
        raw[d][1] = ldg2(p + 8 * L_DIM);
        raw[d][2] = ldg2(p + 8);
        raw[d][3] = ldg2(p + 8 * L_DIM + 8);
    }

    // ldmatrix B per-thread offset
    const int b_nrow = ((lane >> 4) & 1) * 8 + (lane & 7);
    const int b_kb   = ((lane >> 3) & 1) << 4;

    CP_WAIT0();
    __syncthreads();   // B fully resident; the ONLY barrier before the epilogue

    // ---- mainloop: 32 k16 steps, zero barriers, warps fully independent ----
    #pragma unroll
    for (int k16 = 0; k16 < NK16; ++k16) {
        const int buf = k16 % ADEPTH;
        // convert A(k16) raw -> fragments
        uint32_t ah[4];
        {
            __half2 h0 = __float22half2_rn(raw[buf][0]);
            __half2 h1 = __float22half2_rn(raw[buf][1]);
            __half2 h2 = __float22half2_rn(raw[buf][2]);
            __half2 h3 = __float22half2_rn(raw[buf][3]);
            ah[0] = *(uint32_t*)&h0; ah[1] = *(uint32_t*)&h1;
            ah[2] = *(uint32_t*)&h2; ah[3] = *(uint32_t*)&h3;
        }
        // prefetch A(k16+ADEPTH)
        if (k16 + ADEPTH < NK16) {
            const float* p = pA + (k16 + ADEPTH) * 16;
            raw[buf][0] = ldg2(p);
            raw[buf][1] = ldg2(p + 8 * L_DIM);
            raw[buf][2] = ldg2(p + 8);
            raw[buf][3] = ldg2(p + 8 * L_DIM + 8);
        }
        // B from its dedicated smem slot
        const uint32_t bbb = smb + OFF_B + (k16 >> 2) * 16384;
        const int kstep = (k16 & 3) * 32;
        #pragma unroll
        for (int nt2 = 0; nt2 < 4; ++nt2) {
            uint32_t offB = (uint32_t)((Cw + nt2 * 16 + b_nrow) * 128 + kstep + b_kb);
            uint32_t bf[4];
            ldsm_x4(bf[0], bf[1], bf[2], bf[3], bbb + SW128(offB));
            mma_f16(acc[nt2 * 2 + 0], ah, bf[0], bf[1]);
            mma_f16(acc[nt2 * 2 + 1], ah, bf[2], bf[3]);
        }
    }

    // ---- epilogue: bias + dump into smem [128][SSC_PITCH] ----
    if (tid < G_DIM) Sb[tid] = __ldg(&b1[tid]);
    __syncthreads();   // all warps done with B slots before Ssc overwrites them

    const int g  = lane >> 2;
    const int cq = (lane & 3) * 2;
    #pragma unroll
    for (int nt = 0; nt < 8; ++nt) {
        int col = Cw + nt * 8 + cq;
        float2 b2 = *(float2*)&Sb[col];
        int r0 = Rw + g;
        *(float2*)&Ssc[r0 * SSC_PITCH + col] =
            make_float2(acc[nt][0] + b2.x, acc[nt][1] + b2.y);
        *(float2*)&Ssc[(r0 + 8) * SSC_PITCH + col] =
            make_float2(acc[nt][2] + b2.x, acc[nt][3] + b2.y);
    }
    __syncthreads();

    // ---- column cummax over 128 rows: warp w handles 8 columns ----
    {
        const int cw = wid * 8;
        float carry[8];
        #pragma unroll
        for (int j = 0; j < 8; ++j) carry[j] = -FLT_MAX;
        #pragma unroll
        for (int rb = 0; rb < 4; ++rb) {
            int row = rb * 32 + lane;
            float v[8];
            #pragma unroll
            for (int q = 0; q < 2; ++q) {
                float4 x = *(float4*)&Ssc[row * SSC_PITCH + cw + q * 4];
                v[q * 4 + 0] = x.x; v[q * 4 + 1] = x.y;
                v[q * 4 + 2] = x.z; v[q * 4 + 3] = x.w;
            }
            #pragma unroll
            for (int d = 1; d < 32; d <<= 1) {
                #pragma unroll
                for (int j = 0; j < 8; ++j) {
                    float tshf = __shfl_up_sync(0xffffffffu, v[j], d);
                    if (lane >= d) v[j] = fmaxf(v[j], tshf);
                }
            }
            #pragma unroll
            for (int j = 0; j < 8; ++j) v[j] = fmaxf(v[j], carry[j]);
            #pragma unroll
            for (int q = 0; q < 2; ++q) {
                float4 x = make_float4(v[q * 4], v[q * 4 + 1], v[q * 4 + 2], v[q * 4 + 3]);
                *(float4*)&Ssc[row * SSC_PITCH + cw + q * 4] = x;
            }
            #pragma unroll
            for (int j = 0; j < 8; ++j) carry[j] = __shfl_sync(0xffffffffu, v[j], 31);
        }
    }
    __syncthreads();

    // ---- decoupled lookback over tiles (32-wide parallel window) ----
    float incl = -FLT_MAX;
    if (tile == 0) {
        if (tid < G_DIM) {
            float a = Ssc[127 * SSC_PITCH + tid];
            float run = __ldg(&gfeat[tid]);       // seed with global feature
            incl = fmaxf(a, run);
            g_inclusive[tid] = incl;
            Spre[tid] = run;
        }
        __threadfence();
        __syncthreads();
        if (tid == 0) atomicExch(&g_flags[0], 2);
    } else {
        float a = -FLT_MAX;
        if (tid < G_DIM) {
            a = Ssc[127 * SSC_PITCH + tid];
            g_aggregate[(size_t)tile * G_DIM + tid] = a;
        }
        __threadfence();
        __syncthreads();
        if (tid == 0) atomicExch(&g_flags[tile], 1);

        float run = -FLT_MAX;
        int p = tile - 1;
        while (true) {
            if (wid == 0) {
                int idx = p - lane;
                int f = 1;
                if (idx >= 0) {
                    f = ld_flag_cg(&g_flags[idx]);
                    while (f == 0) { __nanosleep(32); f = ld_flag_cg(&g_flags[idx]); }
                }
                unsigned ball = __ballot_sync(0xffffffffu, f == 2);
                if (lane == 0)
                    Sstat[0] = (ball == 0) ? 32 : (__ffs(ball) - 1);
            }
            __syncthreads();
            int l2 = Sstat[0];
            int lstop = (l2 < 32) ? l2 : 31;
            if (tid < G_DIM) {
                for (int l = 0; l <= lstop; ++l) {
                    int idx = p - l;
                    const float* src = (l == l2) ? &g_inclusive[(size_t)idx * G_DIM]
                                                 : &g_aggregate[(size_t)idx * G_DIM];
                    run = fmaxf(run, ld_f_cg(&src[tid]));
                }
            }
            __syncthreads();
            if (l2 < 32) break;
            p -= 32;
        }
        if (tid < G_DIM) {
            incl = fmaxf(run, a);
            g_inclusive[(size_t)tile * G_DIM + tid] = incl;
            Spre[tid] = run;
        }
        __threadfence();
        __syncthreads();
        if (tid == 0) atomicExch(&g_flags[tile], 2);
    }
    __syncthreads();

    // ---- combine with tile prefix, stream out ----
    float* outp = out + (size_t)tile * TILE_ROWS * G_DIM;
    #pragma unroll
    for (int i = 0; i < 8; ++i) {
        int e = tid + i * NTHREADS;               // 0..4095 float4
        int r = e >> 5, c4 = e & 31;
        const float* s  = &Ssc[r * SSC_PITCH + c4 * 4];
        const float* pp = &Spre[c4 * 4];
        float4 o;
        o.x = fmaxf(s[0], pp[0]);
        o.y = fmaxf(s[1], pp[1]);
        o.z = fmaxf(s[2], pp[2]);
        o.w = fmaxf(s[3], pp[3]);
        st_cs4(&outp[e * 4], o);
    }
    if (write_tail && tile == NUM_TILES - 1 && tid < G_DIM)
        out[(size_t)W_TOTAL * G_DIM + tid] = incl;
}

extern "C" void kernel_launch(void* const* d_in, const int* in_sizes, int n_in,
                              void* d_out, int out_size) {
    const float* local = (const float*)d_in[0];  // [262144, 512]
    const float* gfeat = (const float*)d_in[1];  // [1, 128]
    const float* W1    = (const float*)d_in[2];  // [512, 128]
    const float* b1    = (const float*)d_in[3];  // [128]
    float* out = (float*)d_out;

    static int configured = 0;
    if (!configured) {
        cudaFuncSetAttribute(key_pool_mma,
                             cudaFuncAttributeMaxDynamicSharedMemorySize, SMEM_TOTAL);
        configured = 1;
    }
    int write_tail = (out_size >= W_TOTAL * G_DIM + G_DIM) ? 1 : 0;

    prep_kernel<<<256, 256>>>(W1);
    key_pool_mma<<<NUM_TILES, NTHREADS, SMEM_TOTAL>>>(local, gfeat, b1, out, write_tail);
}

// round 10
// speedup vs baseline: 1.1796x; 1.1796x over previous
#include <cuda_runtime.h>
#include <cuda_fp16.h>
#include <cstdint>
#include <cfloat>

#define W_TOTAL   262144
#define L_DIM     512
#define G_DIM     128
#define TILE_ROWS 128
#define NUM_TILES (W_TOTAL / TILE_ROWS)   // 2048
#define NKCH      4                       // K chunks of 128
#define NTHREADS  512

// ---- smem layout (bytes), dynamic smem only ----
#define OFF_B      0                  // B fp16, 8 sub-slots x [128n][64k] = 128 KB, loaded once
#define OFF_A0     131072             // A fp16 chunk (K=128): 2 sub-slots x 16 KB = 32 KB
#define OFF_A1     163840             // ends 196608
#define OFF_SSC    0                  // epilogue reuse: float[128][132] = 67584
#define SSC_PITCH  132
#define OFF_SB     196608             // bias 128 f32
#define OFF_SPRE   197120             // tile prefix 128 f32
#define OFF_STATE  197632             // lookback window state (int)
#define SMEM_TOTAL 197648

// device globals (no runtime allocation allowed)
__device__ __half g_Wh[G_DIM * L_DIM];          // W1^T as fp16, [n][k] k-major
__device__ float  g_aggregate[NUM_TILES * G_DIM];
__device__ float  g_inclusive[NUM_TILES * G_DIM];
__device__ int    g_flags[NUM_TILES];

#define SW128(o) ((o) ^ (((o) >> 3) & 0x70))

// ---- PTX helpers ----
__device__ __forceinline__ uint32_t smem_u32(const void* p) {
    uint32_t a;
    asm("{ .reg .u64 t; cvta.to.shared.u64 t, %1; cvt.u32.u64 %0, t; }" : "=r"(a) : "l"(p));
    return a;
}
__device__ __forceinline__ void ldsm_x4(uint32_t& r0, uint32_t& r1, uint32_t& r2,
                                        uint32_t& r3, uint32_t addr) {
    asm volatile("ldmatrix.sync.aligned.m8n8.x4.shared.b16 {%0,%1,%2,%3}, [%4];"
                 : "=r"(r0), "=r"(r1), "=r"(r2), "=r"(r3) : "r"(addr));
}
__device__ __forceinline__ void mma_f16(float* c, const uint32_t* a, uint32_t b0, uint32_t b1) {
    asm volatile(
        "mma.sync.aligned.m16n8k16.row.col.f32.f16.f16.f32 "
        "{%0,%1,%2,%3}, {%4,%5,%6,%7}, {%8,%9}, {%0,%1,%2,%3};"
        : "+f"(c[0]), "+f"(c[1]), "+f"(c[2]), "+f"(c[3])
        : "r"(a[0]), "r"(a[1]), "r"(a[2]), "r"(a[3]), "r"(b0), "r"(b1));
}
__device__ __forceinline__ void cp_async16(uint32_t dst, const void* src) {
    asm volatile("cp.async.cg.shared.global [%0], [%1], 16;" :: "r"(dst), "l"(src));
}
#define CP_COMMIT() asm volatile("cp.async.commit_group;" ::: "memory")
#define CP_WAIT0()  asm volatile("cp.async.wait_group 0;" ::: "memory")

__device__ __forceinline__ int ld_flag_cg(const int* p) {
    int f; asm volatile("ld.global.cg.b32 %0, [%1];" : "=r"(f) : "l"(p)); return f;
}
__device__ __forceinline__ float ld_f_cg(const float* p) {
    float f; asm volatile("ld.global.cg.f32 %0, [%1];" : "=f"(f) : "l"(p)); return f;
}
__device__ __forceinline__ void st_cs4(float* p, float4 v) {
    asm volatile("st.global.cs.v4.f32 [%0], {%1,%2,%3,%4};"
                 :: "l"(p), "f"(v.x), "f"(v.y), "f"(v.z), "f"(v.w) : "memory");
}

// ---- merged prep kernel (1 launch): W1 -> fp16 transpose, zero flags ----
__global__ void prep_kernel(const float* __restrict__ W1) {   // W1: [512][128]
    int idx = blockIdx.x * 256 + threadIdx.x;                 // 65536
    int k = idx >> 7, n = idx & 127;
    g_Wh[n * L_DIM + k] = __float2half_rn(W1[idx]);
    if (idx < NUM_TILES) g_flags[idx] = 0;
}

// ---- main fused kernel: big-chunk fp16 HMMA GEMM + cummax lookback ----
__global__ void __launch_bounds__(NTHREADS, 1)
key_pool_mma(const float* __restrict__ A,      // [W, L]
             const float* __restrict__ gfeat,  // [G]
             const float* __restrict__ b1,     // [G]
             float* __restrict__ out, int write_tail) {
    extern __shared__ char sm[];
    const uint32_t smb = smem_u32(sm);
    float* Ssc   = (float*)(sm + OFF_SSC);
    float* Sb    = (float*)(sm + OFF_SB);
    float* Spre  = (float*)(sm + OFF_SPRE);
    int*   Sstat = (int*)(sm + OFF_STATE);

    const int tid  = threadIdx.x;
    const int wid  = tid >> 5;
    const int lane = tid & 31;
    const int tile = blockIdx.x;

    const int Rw = (wid & 7) * 16;   // warp row base (0..112)
    const int Cw = (wid >> 3) * 64;  // warp col base (0 or 64)

    const float4* A4 = (const float4*)(A + (size_t)tile * TILE_ROWS * L_DIM);
    const __half* Wh = g_Wh;

    // ---- prologue: cp.async ALL of B (128 KB) once; LDG A chunk 0 ----
    #pragma unroll
    for (int i = 0; i < 16; ++i) {
        int e = tid + i * NTHREADS;              // 0..8191 uint4
        int slot = e >> 10, w = e & 1023;
        int n = w >> 3, u = w & 7;
        cp_async16(smb + OFF_B + slot * 16384 + SW128((uint32_t)(n * 128 + u * 16)),
                   Wh + n * L_DIM + slot * 64 + u * 8);
    }
    CP_COMMIT();

    float acc[8][4];
    #pragma unroll
    for (int n = 0; n < 8; ++n)
        #pragma unroll
        for (int j = 0; j < 4; ++j) acc[n][j] = 0.f;

    // A chunk staging (K=128): per thread 8 float4; e = tid+i*512 -> r=e>>5, q=e&31
    float4 ra[8];
    #pragma unroll
    for (int i = 0; i < 8; ++i) {
        int e = tid + i * NTHREADS, r = e >> 5, q = e & 31;
        ra[i] = __ldg(&A4[r * 128 + q]);
    }

    // ldmatrix per-thread offsets
    const int a_row  = (lane & 15);
    const int a_kb   = (lane >> 4) << 4;
    const int b_nrow = ((lane >> 4) & 1) * 8 + (lane & 7);
    const int b_kb   = ((lane >> 3) & 1) << 4;

    // ---- mainloop: 4 chunks of K=128, ONE barrier per chunk ----
    #pragma unroll
    for (int kc = 0; kc < NKCH; ++kc) {
        char* ahp = sm + ((kc & 1) ? OFF_A1 : OFF_A0);
        const uint32_t ahb = smb + ((kc & 1) ? OFF_A1 : OFF_A0);

        // convert + STS A(kc): sub-slot q>>4, within: r*128 + (q&15)*8
        #pragma unroll
        for (int i = 0; i < 8; ++i) {
            int e = tid + i * NTHREADS, r = e >> 5, q = e & 31;
            __half2 h01 = __float22half2_rn(make_float2(ra[i].x, ra[i].y));
            __half2 h23 = __float22half2_rn(make_float2(ra[i].z, ra[i].w));
            *(uint2*)(ahp + (q >> 4) * 16384 + SW128((uint32_t)(r * 128 + (q & 15) * 8))) =
                make_uint2(*(uint32_t*)&h01, *(uint32_t*)&h23);
        }
        // prefetch A(kc+1)
        if (kc < NKCH - 1) {
            #pragma unroll
            for (int i = 0; i < 8; ++i) {
                int e = tid + i * NTHREADS, r = e >> 5, q = e & 31;
                ra[i] = __ldg(&A4[r * 128 + (kc + 1) * 32 + q]);
            }
        }
        if (kc == 0) CP_WAIT0();   // B resident
        __syncthreads();           // A(kc) staged everywhere; MMA(kc-1) reads complete

        // ---- 8 uninterrupted k16 steps ----
        #pragma unroll
        for (int j = 0; j < 8; ++j) {
            uint32_t ah[4];
            {
                uint32_t offA = (uint32_t)((Rw + a_row) * 128 + (j & 3) * 32 + a_kb);
                ldsm_x4(ah[0], ah[1], ah[2], ah[3],
                        ahb + (j >> 2) * 16384 + SW128(offA));
            }
            const uint32_t bbb = smb + OFF_B + (kc * 2 + (j >> 2)) * 16384;
            const int kstep = (j & 3) * 32;
            #pragma unroll
            for (int nt2 = 0; nt2 < 4; ++nt2) {
                uint32_t offB = (uint32_t)((Cw + nt2 * 16 + b_nrow) * 128 + kstep + b_kb);
                uint32_t bf[4];
                ldsm_x4(bf[0], bf[1], bf[2], bf[3], bbb + SW128(offB));
                mma_f16(acc[nt2 * 2 + 0], ah, bf[0], bf[1]);
                mma_f16(acc[nt2 * 2 + 1], ah, bf[2], bf[3]);
            }
        }
    }

    // ---- epilogue: bias + dump into smem [128][SSC_PITCH] ----
    if (tid < G_DIM) Sb[tid] = __ldg(&b1[tid]);
    __syncthreads();   // all warps done with B/A slots before Ssc overwrites

    const int g  = lane >> 2;
    const int cq = (lane & 3) * 2;
    #pragma unroll
    for (int nt = 0; nt < 8; ++nt) {
        int col = Cw + nt * 8 + cq;
        float2 b2 = *(float2*)&Sb[col];
        int r0 = Rw + g;
        *(float2*)&Ssc[r0 * SSC_PITCH + col] =
            make_float2(acc[nt][0] + b2.x, acc[nt][1] + b2.y);
        *(float2*)&Ssc[(r0 + 8) * SSC_PITCH + col] =
            make_float2(acc[nt][2] + b2.x, acc[nt][3] + b2.y);
    }
    __syncthreads();

    // ---- column cummax over 128 rows: warp w handles 8 columns ----
    {
        const int cw = wid * 8;
        float carry[8];
        #pragma unroll
        for (int j = 0; j < 8; ++j) carry[j] = -FLT_MAX;
        #pragma unroll
        for (int rb = 0; rb < 4; ++rb) {
            int row = rb * 32 + lane;
            float v[8];
            #pragma unroll
            for (int q = 0; q < 2; ++q) {
                float4 x = *(float4*)&Ssc[row * SSC_PITCH + cw + q * 4];
                v[q * 4 + 0] = x.x; v[q * 4 + 1] = x.y;
                v[q * 4 + 2] = x.z; v[q * 4 + 3] = x.w;
            }
            #pragma unroll
            for (int d = 1; d < 32; d <<= 1) {
                #pragma unroll
                for (int j = 0; j < 8; ++j) {
                    float tshf = __shfl_up_sync(0xffffffffu, v[j], d);
                    if (lane >= d) v[j] = fmaxf(v[j], tshf);
                }
            }
            #pragma unroll
            for (int j = 0; j < 8; ++j) v[j] = fmaxf(v[j], carry[j]);
            #pragma unroll
            for (int q = 0; q < 2; ++q) {
                float4 x = make_float4(v[q * 4], v[q * 4 + 1], v[q * 4 + 2], v[q * 4 + 3]);
                *(float4*)&Ssc[row * SSC_PITCH + cw + q * 4] = x;
            }
            #pragma unroll
            for (int j = 0; j < 8; ++j) carry[j] = __shfl_sync(0xffffffffu, v[j], 31);
        }
    }
    __syncthreads();

    // ---- decoupled lookback over tiles (32-wide parallel window) ----
    float incl = -FLT_MAX;
    if (tile == 0) {
        if (tid < G_DIM) {
            float a = Ssc[127 * SSC_PITCH + tid];
            float run = __ldg(&gfeat[tid]);       // seed with global feature
            incl = fmaxf(a, run);
            g_inclusive[tid] = incl;
            Spre[tid] = run;
        }
        __threadfence();
        __syncthreads();
        if (tid == 0) atomicExch(&g_flags[0], 2);
    } else {
        float a = -FLT_MAX;
        if (tid < G_DIM) {
            a = Ssc[127 * SSC_PITCH + tid];
            g_aggregate[(size_t)tile * G_DIM + tid] = a;
        }
        __threadfence();
        __syncthreads();
        if (tid == 0) atomicExch(&g_flags[tile], 1);

        float run = -FLT_MAX;
        int p = tile - 1;
        while (true) {
            if (wid == 0) {
                int idx = p - lane;
                int f = 1;
                if (idx >= 0) {
                    f = ld_flag_cg(&g_flags[idx]);
                    while (f == 0) { __nanosleep(32); f = ld_flag_cg(&g_flags[idx]); }
                }
                unsigned ball = __ballot_sync(0xffffffffu, f == 2);
                if (lane == 0)
                    Sstat[0] = (ball == 0) ? 32 : (__ffs(ball) - 1);
            }
            __syncthreads();
            int l2 = Sstat[0];
            int lstop = (l2 < 32) ? l2 : 31;
            if (tid < G_DIM) {
                for (int l = 0; l <= lstop; ++l) {
                    int idx = p - l;
                    const float* src = (l == l2) ? &g_inclusive[(size_t)idx * G_DIM]
                                                 : &g_aggregate[(size_t)idx * G_DIM];
                    run = fmaxf(run, ld_f_cg(&src[tid]));
                }
            }
            __syncthreads();
            if (l2 < 32) break;
            p -= 32;
        }
        if (tid < G_DIM) {
            incl = fmaxf(run, a);
            g_inclusive[(size_t)tile * G_DIM + tid] = incl;
            Spre[tid] = run;
        }
        __threadfence();
        __syncthreads();
        if (tid == 0) atomicExch(&g_flags[tile], 2);
    }
    __syncthreads();

    // ---- combine with tile prefix, stream out ----
    float* outp = out + (size_t)tile * TILE_ROWS * G_DIM;
    #pragma unroll
    for (int i = 0; i < 8; ++i) {
        int e = tid + i * NTHREADS;               // 0..4095 float4
        int r = e >> 5, c4 = e & 31;
        const float* s  = &Ssc[r * SSC_PITCH + c4 * 4];
        const float* pp = &Spre[c4 * 4];
        float4 o;
        o.x = fmaxf(s[0], pp[0]);
        o.y = fmaxf(s[1], pp[1]);
        o.z = fmaxf(s[2], pp[2]);
        o.w = fmaxf(s[3], pp[3]);
        st_cs4(&outp[e * 4], o);
    }
    if (write_tail && tile == NUM_TILES - 1 && tid < G_DIM)
        out[(size_t)W_TOTAL * G_DIM + tid] = incl;
}

extern "C" void kernel_launch(void* const* d_in, const int* in_sizes, int n_in,
                              void* d_out, int out_size) {
    const float* local = (const float*)d_in[0];  // [262144, 512]
    const float* gfeat = (const float*)d_in[1];  // [1, 128]
    const float* W1    = (const float*)d_in[2];  // [512, 128]
    const float* b1    = (const float*)d_in[3];  // [128]
    float* out = (float*)d_out;

    static int configured = 0;
    if (!configured) {
        cudaFuncSetAttribute(key_pool_mma,
                             cudaFuncAttributeMaxDynamicSharedMemorySize, SMEM_TOTAL);
        configured = 1;
    }
    int write_tail = (out_size >= W_TOTAL * G_DIM + G_DIM) ? 1 : 0;

    prep_kernel<<<256, 256>>>(W1);
    key_pool_mma<<<NUM_TILES, NTHREADS, SMEM_TOTAL>>>(local, gfeat, b1, out, write_tail);
}

// round 11
// speedup vs baseline: 1.1910x; 1.0097x over previous
#include <cuda_runtime.h>
#include <cuda_fp16.h>
#include <cstdint>
#include <cfloat>

#define W_TOTAL   262144
#define L_DIM     512
#define G_DIM     128
#define TILE_ROWS 128
#define NUM_TILES (W_TOTAL / TILE_ROWS)   // 2048
#define NKCH      4                       // K chunks of 128
#define NTHREADS  512

// ---- smem layout (bytes), dynamic smem only ----
#define OFF_B      0                  // B fp16, 8 sub-slots x [128n][64k] = 128 KB, loaded once
#define OFF_A0     131072             // A fp16 chunk (K=128): 2 sub-slots x 16 KB = 32 KB
#define OFF_A1     163840             // ends 196608
#define OFF_SSC    0                  // epilogue reuse: float[128][132] = 67584
#define SSC_PITCH  132
#define OFF_SB     196608             // bias 128 f32
#define OFF_SPRE   197120             // tile prefix 128 f32
#define OFF_STATE  197632             // lookback window state (int)
#define SMEM_TOTAL 197648

// device globals (no runtime allocation allowed)
__device__ __half g_Wh[G_DIM * L_DIM];          // W1^T as fp16, [n][k] k-major
__device__ float  g_aggregate[NUM_TILES * G_DIM];
__device__ float  g_inclusive[NUM_TILES * G_DIM];
__device__ int    g_flags[NUM_TILES];

#define SW128(o) ((o) ^ (((o) >> 3) & 0x70))

// ---- PTX helpers ----
__device__ __forceinline__ uint32_t smem_u32(const void* p) {
    uint32_t a;
    asm("{ .reg .u64 t; cvta.to.shared.u64 t, %1; cvt.u32.u64 %0, t; }" : "=r"(a) : "l"(p));
    return a;
}
__device__ __forceinline__ void ldsm_x4(uint32_t& r0, uint32_t& r1, uint32_t& r2,
                                        uint32_t& r3, uint32_t addr) {
    asm volatile("ldmatrix.sync.aligned.m8n8.x4.shared.b16 {%0,%1,%2,%3}, [%4];"
                 : "=r"(r0), "=r"(r1), "=r"(r2), "=r"(r3) : "r"(addr));
}
__device__ __forceinline__ void mma_f16(float* c, const uint32_t* a, uint32_t b0, uint32_t b1) {
    asm volatile(
        "mma.sync.aligned.m16n8k16.row.col.f32.f16.f16.f32 "
        "{%0,%1,%2,%3}, {%4,%5,%6,%7}, {%8,%9}, {%0,%1,%2,%3};"
        : "+f"(c[0]), "+f"(c[1]), "+f"(c[2]), "+f"(c[3])
        : "r"(a[0]), "r"(a[1]), "r"(a[2]), "r"(a[3]), "r"(b0), "r"(b1));
}
__device__ __forceinline__ void cp_async16(uint32_t dst, const void* src) {
    asm volatile("cp.async.cg.shared.global [%0], [%1], 16;" :: "r"(dst), "l"(src));
}
#define CP_COMMIT() asm volatile("cp.async.commit_group;" ::: "memory")
#define CP_WAIT0()  asm volatile("cp.async.wait_group 0;" ::: "memory")

__device__ __forceinline__ int ld_flag_cg(const int* p) {
    int f; asm volatile("ld.global.cg.b32 %0, [%1];" : "=r"(f) : "l"(p)); return f;
}
__device__ __forceinline__ float ld_f_cg(const float* p) {
    float f; asm volatile("ld.global.cg.f32 %0, [%1];" : "=f"(f) : "l"(p)); return f;
}
__device__ __forceinline__ void st_cs4(float* p, float4 v) {
    asm volatile("st.global.cs.v4.f32 [%0], {%1,%2,%3,%4};"
                 :: "l"(p), "f"(v.x), "f"(v.y), "f"(v.z), "f"(v.w) : "memory");
}

// ---- merged prep kernel (1 launch): W1 -> fp16 transpose, zero flags ----
__global__ void prep_kernel(const float* __restrict__ W1) {   // W1: [512][128]
    int idx = blockIdx.x * 256 + threadIdx.x;                 // 65536
    int k = idx >> 7, n = idx & 127;
    g_Wh[n * L_DIM + k] = __float2half_rn(W1[idx]);
    if (idx < NUM_TILES) g_flags[idx] = 0;
}

// ---- main fused kernel: fragment-pipelined fp16 HMMA GEMM + cummax lookback ----
__global__ void __launch_bounds__(NTHREADS, 1)
key_pool_mma(const float* __restrict__ A,      // [W, L]
             const float* __restrict__ gfeat,  // [G]
             const float* __restrict__ b1,     // [G]
             float* __restrict__ out, int write_tail) {
    extern __shared__ char sm[];
    const uint32_t smb = smem_u32(sm);
    float* Ssc   = (float*)(sm + OFF_SSC);
    float* Sb    = (float*)(sm + OFF_SB);
    float* Spre  = (float*)(sm + OFF_SPRE);
    int*   Sstat = (int*)(sm + OFF_STATE);

    const int tid  = threadIdx.x;
    const int wid  = tid >> 5;
    const int lane = tid & 31;
    const int tile = blockIdx.x;

    const int Rw = (wid & 7) * 16;   // warp row base (0..112)
    const int Cw = (wid >> 3) * 64;  // warp col base (0 or 64)

    const float4* A4 = (const float4*)(A + (size_t)tile * TILE_ROWS * L_DIM);
    const __half* Wh = g_Wh;

    // ---- prologue: cp.async ALL of B (128 KB) once; LDG A chunk 0 ----
    #pragma unroll
    for (int i = 0; i < 16; ++i) {
        int e = tid + i * NTHREADS;              // 0..8191 uint4
        int slot = e >> 10, w = e & 1023;
        int n = w >> 3, u = w & 7;
        cp_async16(smb + OFF_B + slot * 16384 + SW128((uint32_t)(n * 128 + u * 16)),
                   Wh + n * L_DIM + slot * 64 + u * 8);
    }
    CP_COMMIT();

    float acc[8][4];
    #pragma unroll
    for (int n = 0; n < 8; ++n)
        #pragma unroll
        for (int j = 0; j < 4; ++j) acc[n][j] = 0.f;

    // A chunk staging (K=128): per thread 8 float4; e = tid+i*512 -> r=e>>5, q=e&31
    float4 ra[8];
    #pragma unroll
    for (int i = 0; i < 8; ++i) {
        int e = tid + i * NTHREADS, r = e >> 5, q = e & 31;
        ra[i] = __ldg(&A4[r * 128 + q]);
    }

    // ldmatrix per-thread offsets
    const int a_row  = (lane & 15);
    const int a_kb   = (lane >> 4) << 4;
    const int b_nrow = ((lane >> 4) & 1) * 8 + (lane & 7);
    const int b_kb   = ((lane >> 3) & 1) << 4;

    // fragment double buffers
    uint32_t ah[2][4];
    uint32_t bf[2][4][4];

    // ---- mainloop: 4 chunks of K=128, ONE barrier per chunk ----
    #pragma unroll
    for (int kc = 0; kc < NKCH; ++kc) {
        char* ahp = sm + ((kc & 1) ? OFF_A1 : OFF_A0);
        const uint32_t ahb = smb + ((kc & 1) ? OFF_A1 : OFF_A0);

        // convert + STS A(kc): sub-slot q>>4, within: r*128 + (q&15)*8
        #pragma unroll
        for (int i = 0; i < 8; ++i) {
            int e = tid + i * NTHREADS, r = e >> 5, q = e & 31;
            __half2 h01 = __float22half2_rn(make_float2(ra[i].x, ra[i].y));
            __half2 h23 = __float22half2_rn(make_float2(ra[i].z, ra[i].w));
            *(uint2*)(ahp + (q >> 4) * 16384 + SW128((uint32_t)(r * 128 + (q & 15) * 8))) =
                make_uint2(*(uint32_t*)&h01, *(uint32_t*)&h23);
        }
        // prefetch A(kc+1)
        if (kc < NKCH - 1) {
            #pragma unroll
            for (int i = 0; i < 8; ++i) {
                int e = tid + i * NTHREADS, r = e >> 5, q = e & 31;
                ra[i] = __ldg(&A4[r * 128 + (kc + 1) * 32 + q]);
            }
        }
        if (kc == 0) CP_WAIT0();   // B resident
        __syncthreads();           // A(kc) staged everywhere; MMA(kc-1) reads complete

        // ---- warm fragments for j=0 ----
        {
            uint32_t offA = (uint32_t)((Rw + a_row) * 128 + a_kb);
            ldsm_x4(ah[0][0], ah[0][1], ah[0][2], ah[0][3], ahb + SW128(offA));
        }
        if (kc == 0) {             // kc>0: bf[0] was prefetched at prev chunk's j=7
            const uint32_t bbb0 = smb + OFF_B + (kc * 2) * 16384;
            #pragma unroll
            for (int nt2 = 0; nt2 < 4; ++nt2) {
                uint32_t offB = (uint32_t)((Cw + nt2 * 16 + b_nrow) * 128 + b_kb);
                ldsm_x4(bf[0][nt2][0], bf[0][nt2][1], bf[0][nt2][2], bf[0][nt2][3],
                        bbb0 + SW128(offB));
            }
        }

        // ---- 8 k16 steps, fragments double-buffered: LDSM(j+1) before MMA(j) ----
        #pragma unroll
        for (int j = 0; j < 8; ++j) {
            const int cur = j & 1, nxt = cur ^ 1;
            // prefetch fragments for j+1
            if (j < 7) {
                uint32_t offA = (uint32_t)((Rw + a_row) * 128 + ((j + 1) & 3) * 32 + a_kb);
                ldsm_x4(ah[nxt][0], ah[nxt][1], ah[nxt][2], ah[nxt][3],
                        ahb + ((j + 1) >> 2) * 16384 + SW128(offA));
                const uint32_t bbn = smb + OFF_B + (kc * 2 + ((j + 1) >> 2)) * 16384;
                const int ksn = ((j + 1) & 3) * 32;
                #pragma unroll
                for (int nt2 = 0; nt2 < 4; ++nt2) {
                    uint32_t offB = (uint32_t)((Cw + nt2 * 16 + b_nrow) * 128 + ksn + b_kb);
                    ldsm_x4(bf[nxt][nt2][0], bf[nxt][nt2][1], bf[nxt][nt2][2], bf[nxt][nt2][3],
                            bbn + SW128(offB));
                }
            } else if (kc < NKCH - 1) {
                // cross-chunk B prefetch (B resident; A frag loaded after next barrier)
                const uint32_t bbn = smb + OFF_B + ((kc + 1) * 2) * 16384;
                #pragma unroll
                for (int nt2 = 0; nt2 < 4; ++nt2) {
                    uint32_t offB = (uint32_t)((Cw + nt2 * 16 + b_nrow) * 128 + b_kb);
                    ldsm_x4(bf[nxt][nt2][0], bf[nxt][nt2][1], bf[nxt][nt2][2], bf[nxt][nt2][3],
                            bbn + SW128(offB));
                }
            }
            // MMAs on current fragments (loaded a full iteration ago)
            #pragma unroll
            for (int nt2 = 0; nt2 < 4; ++nt2) {
                mma_f16(acc[nt2 * 2 + 0], ah[cur], bf[cur][nt2][0], bf[cur][nt2][1]);
                mma_f16(acc[nt2 * 2 + 1], ah[cur], bf[cur][nt2][2], bf[cur][nt2][3]);
            }
        }
    }

    // ---- epilogue: bias + dump into smem [128][SSC_PITCH] ----
    if (tid < G_DIM) Sb[tid] = __ldg(&b1[tid]);
    __syncthreads();   // all warps done with B/A slots before Ssc overwrites

    const int g  = lane >> 2;
    const int cq = (lane & 3) * 2;
    #pragma unroll
    for (int nt = 0; nt < 8; ++nt) {
        int col = Cw + nt * 8 + cq;
        float2 b2 = *(float2*)&Sb[col];
        int r0 = Rw + g;
        *(float2*)&Ssc[r0 * SSC_PITCH + col] =
            make_float2(acc[nt][0] + b2.x, acc[nt][1] + b2.y);
        *(float2*)&Ssc[(r0 + 8) * SSC_PITCH + col] =
            make_float2(acc[nt][2] + b2.x, acc[nt][3] + b2.y);
    }
    __syncthreads();

    // ---- column cummax over 128 rows: warp w handles 8 columns ----
    {
        const int cw = wid * 8;
        float carry[8];
        #pragma unroll
        for (int j = 0; j < 8; ++j) carry[j] = -FLT_MAX;
        #pragma unroll
        for (int rb = 0; rb < 4; ++rb) {
            int row = rb * 32 + lane;
            float v[8];
            #pragma unroll
            for (int q = 0; q < 2; ++q) {
                float4 x = *(float4*)&Ssc[row * SSC_PITCH + cw + q * 4];
                v[q * 4 + 0] = x.x; v[q * 4 + 1] = x.y;
                v[q * 4 + 2] = x.z; v[q * 4 + 3] = x.w;
            }
            #pragma unroll
            for (int d = 1; d < 32; d <<= 1) {
                #pragma unroll
                for (int j = 0; j < 8; ++j) {
                    float tshf = __shfl_up_sync(0xffffffffu, v[j], d);
                    if (lane >= d) v[j] = fmaxf(v[j], tshf);
                }
            }
            #pragma unroll
            for (int j = 0; j < 8; ++j) v[j] = fmaxf(v[j], carry[j]);
            #pragma unroll
            for (int q = 0; q < 2; ++q) {
                float4 x = make_float4(v[q * 4], v[q * 4 + 1], v[q * 4 + 2], v[q * 4 + 3]);
                *(float4*)&Ssc[row * SSC_PITCH + cw + q * 4] = x;
            }
            #pragma unroll
            for (int j = 0; j < 8; ++j) carry[j] = __shfl_sync(0xffffffffu, v[j], 31);
        }
    }
    __syncthreads();

    // ---- decoupled lookback over tiles (32-wide parallel window) ----
    float incl = -FLT_MAX;
    if (tile == 0) {
        if (tid < G_DIM) {
            float a = Ssc[127 * SSC_PITCH + tid];
            float run = __ldg(&gfeat[tid]);       // seed with global feature
            incl = fmaxf(a, run);
            g_inclusive[tid] = incl;
            Spre[tid] = run;
        }
        __threadfence();
        __syncthreads();
        if (tid == 0) atomicExch(&g_flags[0], 2);
    } else {
        float a = -FLT_MAX;
        if (tid < G_DIM) {
            a = Ssc[127 * SSC_PITCH + tid];
            g_aggregate[(size_t)tile * G_DIM + tid] = a;
        }
        __threadfence();
        __syncthreads();
        if (tid == 0) atomicExch(&g_flags[tile], 1);

        float run = -FLT_MAX;
        int p = tile - 1;
        while (true) {
            if (wid == 0) {
                int idx = p - lane;
                int f = 1;
                if (idx >= 0) {
                    f = ld_flag_cg(&g_flags[idx]);
                    while (f == 0) { __nanosleep(32); f = ld_flag_cg(&g_flags[idx]); }
                }
                unsigned ball = __ballot_sync(0xffffffffu, f == 2);
                if (lane == 0)
                    Sstat[0] = (ball == 0) ? 32 : (__ffs(ball) - 1);
            }
            __syncthreads();
            int l2 = Sstat[0];
            int lstop = (l2 < 32) ? l2 : 31;
            if (tid < G_DIM) {
                for (int l = 0; l <= lstop; ++l) {
                    int idx = p - l;
                    const float* src = (l == l2) ? &g_inclusive[(size_t)idx * G_DIM]
                                                 : &g_aggregate[(size_t)idx * G_DIM];
                    run = fmaxf(run, ld_f_cg(&src[tid]));
                }
            }
            __syncthreads();
            if (l2 < 32) break;
            p -= 32;
        }
        if (tid < G_DIM) {
            incl = fmaxf(run, a);
            g_inclusive[(size_t)tile * G_DIM + tid] = incl;
            Spre[tid] = run;
        }
        __threadfence();
        __syncthreads();
        if (tid == 0) atomicExch(&g_flags[tile], 2);
    }
    __syncthreads();

    // ---- combine with tile prefix, stream out ----
    float* outp = out + (size_t)tile * TILE_ROWS * G_DIM;
    #pragma unroll
    for (int i = 0; i < 8; ++i) {
        int e = tid + i * NTHREADS;               // 0..4095 float4
        int r = e >> 5, c4 = e & 31;
        const float* s  = &Ssc[r * SSC_PITCH + c4 * 4];
        const float* pp = &Spre[c4 * 4];
        float4 o;
        o.x = fmaxf(s[0], pp[0]);
        o.y = fmaxf(s[1], pp[1]);
        o.z = fmaxf(s[2], pp[2]);
        o.w = fmaxf(s[3], pp[3]);
        st_cs4(&outp[e * 4], o);
    }
    if (write_tail && tile == NUM_TILES - 1 && tid < G_DIM)
        out[(size_t)W_TOTAL * G_DIM + tid] = incl;
}

extern "C" void kernel_launch(void* const* d_in, const int* in_sizes, int n_in,
                              void* d_out, int out_size) {
    const float* local = (const float*)d_in[0];  // [262144, 512]
    const float* gfeat = (const float*)d_in[1];  // [1, 128]
    const float* W1    = (const float*)d_in[2];  // [512, 128]
    const float* b1    = (const float*)d_in[3];  // [128]
    float* out = (float*)d_out;

    static int configured = 0;
    if (!configured) {
        cudaFuncSetAttribute(key_pool_mma,
                             cudaFuncAttributeMaxDynamicSharedMemorySize, SMEM_TOTAL);
        configured = 1;
    }
    int write_tail = (out_size >= W_TOTAL * G_DIM + G_DIM) ? 1 : 0;

    prep_kernel<<<256, 256>>>(W1);
    key_pool_mma<<<NUM_TILES, NTHREADS, SMEM_TOTAL>>>(local, gfeat, b1, out, write_tail);
}